// round 2
// baseline (speedup 1.0000x reference)
#include <cuda_runtime.h>
#include <cuda_bf16.h>
#include <cstdint>

// WatermarkLayer: 50 Adam steps per row, one warp per row, state in registers.
// Round 2: f32x2 packed FMA math (FFMA2) + B/beta rescaling to halve FMA-pipe
// pressure; kernel should now sit on the MUFU (sqrt+rcp) floor.
//
// Math notes:
//  - cos_theta == 1.0f exactly in fp32 => hinge = ||mu|| - dot.
//  - hinge>0 gate is per-row => warp-uniform branch.
//  - B-scaling: G = mu*rn - w (= B*g), M = 10*B*m, V = 1000*B^2*v,
//    eps' = eps*B; update = mu += at*M*(1/(sqrt(V*c2)+eps')),
//    at = -LR*0.1/(1-b1^t), c2 = 0.001/(1-b2^t).

#define DLAT 512
#define PPL 8          // f32x2 pairs per lane (512 / 32 / 2)
#define NSTEPS 50
#define MAXB 131072

__device__ float g_rowloss[MAXB];

typedef unsigned long long ull;

__device__ __forceinline__ ull pk(float lo, float hi) {
    ull r; asm("mov.b64 %0, {%1,%2};" : "=l"(r) : "f"(lo), "f"(hi)); return r;
}
__device__ __forceinline__ void upk(float& lo, float& hi, ull x) {
    asm("mov.b64 {%0,%1}, %2;" : "=f"(lo), "=f"(hi) : "l"(x));
}
__device__ __forceinline__ ull fma2(ull a, ull b, ull c) {
    ull d; asm("fma.rn.f32x2 %0, %1, %2, %3;" : "=l"(d) : "l"(a), "l"(b), "l"(c)); return d;
}
__device__ __forceinline__ ull mul2(ull a, ull b) {
    ull d; asm("mul.rn.f32x2 %0, %1, %2;" : "=l"(d) : "l"(a), "l"(b)); return d;
}
__device__ __forceinline__ ull add2(ull a, ull b) {
    ull d; asm("add.rn.f32x2 %0, %1, %2;" : "=l"(d) : "l"(a), "l"(b)); return d;
}
__device__ __forceinline__ float rcp_fast(float x)  { float y; asm("rcp.approx.f32 %0, %1;"   : "=f"(y) : "f"(x)); return y; }
__device__ __forceinline__ float sqrt_fast(float x) { float y; asm("sqrt.approx.f32 %0, %1;"  : "=f"(y) : "f"(x)); return y; }
__device__ __forceinline__ float rsqrt_fast(float x){ float y; asm("rsqrt.approx.f32 %0, %1;" : "=f"(y) : "f"(x)); return y; }

__global__ __launch_bounds__(256)
void wm_adam_kernel(const float* __restrict__ mu,
                    const float* __restrict__ carrier,
                    float* __restrict__ out_mu,
                    float* __restrict__ rowloss,
                    int B)
{
    const int warp = (blockIdx.x * blockDim.x + threadIdx.x) >> 5;
    const int lane = threadIdx.x & 31;
    if (warp >= B) return;

    const float4* murow = reinterpret_cast<const float4*>(mu + (size_t)warp * DLAT);
    const float4* wrow  = reinterpret_cast<const float4*>(carrier);

    ull mu2[PPL], nw2[PPL], M2[PPL], V2[PPL];
    #pragma unroll
    for (int k = 0; k < 4; k++) {
        float4 a = murow[lane + 32 * k];
        float4 b = wrow[lane + 32 * k];
        mu2[2*k]   = pk(a.x, a.y);
        mu2[2*k+1] = pk(a.z, a.w);
        nw2[2*k]   = pk(-b.x, -b.y);
        nw2[2*k+1] = pk(-b.z, -b.w);
    }
    #pragma unroll
    for (int i = 0; i < PPL; i++) { M2[i] = 0ull; V2[i] = 0ull; }

    const float E = 1e-8f * (float)B;          // B-scaled epsilon (exact: B = 2^k)
    const ull C09   = pk(0.9f, 0.9f);
    const ull C0999 = pk(0.999f, 0.999f);

    float pb1 = 1.0f, pb2 = 1.0f;
    float lossv = 0.0f;

    #pragma unroll 1
    for (int t = 1; t <= NSTEPS; t++) {
        pb1 *= 0.9f;
        pb2 *= 0.999f;
        const float at_s = -0.001f * rcp_fast(1.0f - pb1);  // -LR*0.1/(1-b1^t)
        const float c2_s =  0.001f * rcp_fast(1.0f - pb2);  // 0.001/(1-b2^t)
        const ull at2 = pk(at_s, at_s);
        const ull c2p = pk(c2_s, c2_s);

        // packed partials: (-dot, ||mu||^2)
        ull accd = 0ull, accn = 0ull;
        #pragma unroll
        for (int i = 0; i < PPL; i++) {
            accd = fma2(mu2[i], nw2[i], accd);   // accumulates -dot
            accn = fma2(mu2[i], mu2[i], accn);
        }
        float d0, d1, n0, n1;
        upk(d0, d1, accd);
        upk(n0, n1, accn);
        ull P = pk(d0 + d1, n0 + n1);
        #pragma unroll
        for (int o = 16; o > 0; o >>= 1)
            P = add2(P, __shfl_xor_sync(0xFFFFFFFFu, P, o));
        float dneg, nsq;
        upk(dneg, nsq, P);

        const float rn    = rsqrt_fast(nsq);
        const float hinge = fmaf(nsq, rn, dneg);   // ||mu|| - dot

        if (hinge > 0.0f) {
            lossv = hinge;
            const ull rn2 = pk(rn, rn);
            #pragma unroll
            for (int i = 0; i < PPL; i++) {
                ull g  = fma2(mu2[i], rn2, nw2[i]);       // mu/|mu| - w  (B-scaled grad)
                ull gg = mul2(g, g);
                M2[i] = fma2(C09,   M2[i], g);
                V2[i] = fma2(C0999, V2[i], gg);
                ull vh = mul2(V2[i], c2p);
                float v0, v1; upk(v0, v1, vh);
                float i0 = rcp_fast(sqrt_fast(v0) + E);
                float i1 = rcp_fast(sqrt_fast(v1) + E);
                ull di = pk(i0, i1);
                ull st = mul2(M2[i], at2);
                mu2[i] = fma2(st, di, mu2[i]);
            }
        } else {
            lossv = 0.0f;
            #pragma unroll
            for (int i = 0; i < PPL; i++) {
                M2[i] = mul2(C09,   M2[i]);               // g = 0 path
                V2[i] = mul2(C0999, V2[i]);
                ull vh = mul2(V2[i], c2p);
                float v0, v1; upk(v0, v1, vh);
                float i0 = rcp_fast(sqrt_fast(v0) + E);
                float i1 = rcp_fast(sqrt_fast(v1) + E);
                ull di = pk(i0, i1);
                ull st = mul2(M2[i], at2);
                mu2[i] = fma2(st, di, mu2[i]);
            }
        }
    }

    float4* outrow = reinterpret_cast<float4*>(out_mu + (size_t)warp * DLAT);
    #pragma unroll
    for (int k = 0; k < 4; k++) {
        float4 a;
        upk(a.x, a.y, mu2[2*k]);
        upk(a.z, a.w, mu2[2*k+1]);
        outrow[lane + 32 * k] = a;
    }
    if (lane == 0) rowloss[warp] = lossv;
}

// Deterministic single-block reduction: loss = mean(rowloss)
__global__ __launch_bounds__(1024)
void wm_reduce_loss(const float* __restrict__ rowloss, float* __restrict__ out, int B)
{
    __shared__ float sh[1024];
    float s = 0.0f;
    for (int i = threadIdx.x; i < B; i += 1024) s += rowloss[i];
    sh[threadIdx.x] = s;
    __syncthreads();
    #pragma unroll
    for (int o = 512; o > 0; o >>= 1) {
        if (threadIdx.x < o) sh[threadIdx.x] += sh[threadIdx.x + o];
        __syncthreads();
    }
    if (threadIdx.x == 0) out[0] = sh[0] * (1.0f / (float)B);
}

extern "C" void kernel_launch(void* const* d_in, const int* in_sizes, int n_in,
                              void* d_out, int out_size)
{
    const float* mu      = (const float*)d_in[0];
    const float* log_var = (const float*)d_in[1];
    const float* carrier = (const float*)d_in[2];
    float* out = (float*)d_out;

    const int B = in_sizes[0] / DLAT;
    float* out_mu   = out;
    float* out_lv   = out + (size_t)B * DLAT;
    float* out_loss = out + (size_t)out_size - 1;

    float* rowloss;
    cudaGetSymbolAddress((void**)&rowloss, g_rowloss);

    cudaMemcpyAsync(out_lv, log_var, (size_t)B * DLAT * sizeof(float),
                    cudaMemcpyDeviceToDevice, 0);

    const int blocks = (B + 7) / 8;
    wm_adam_kernel<<<blocks, 256>>>(mu, carrier, out_mu, rowloss, B);

    wm_reduce_loss<<<1, 1024>>>(rowloss, out_loss, B);
}

// round 7
// speedup vs baseline: 1.0865x; 1.0865x over previous
#include <cuda_runtime.h>
#include <cuda_bf16.h>
#include <cstdint>

// WatermarkLayer: 50 Adam steps per row, one warp per row, state in registers.
// Round 3: scalar fp32 (packing proved throughput-neutral on sm_103a),
// B/beta rescaling to reach 9 FMA-pipe ops + 2 MUFU per element-step.
//
// Scaled recursion (exact-eps semantics preserved):
//   G = B*g = [hinge>0]*(mu*rn - w),  M_t = b1*M + G,  V_t = b2*V + G^2
//   den = sqrt(V)*s2 + E,  E = eps*B (exact, B=2^17),
//   s2 = sqrt(0.001/(1-b2^t)),  a_t = -0.001/(1-b1^t)
//   mu += a_t * M / den
// cos_theta == 1.0f exactly in fp32 => hinge = ||mu|| - dot (warp-uniform gate).

#define DLAT 512
#define EPL 16
#define NSTEPS 50
#define MAXB 131072

__device__ float g_rowloss[MAXB];

__device__ __forceinline__ float rcp_fast(float x)  { float y; asm("rcp.approx.f32 %0, %1;"   : "=f"(y) : "f"(x)); return y; }
__device__ __forceinline__ float sqrt_fast(float x) { float y; asm("sqrt.approx.f32 %0, %1;"  : "=f"(y) : "f"(x)); return y; }
__device__ __forceinline__ float rsqrt_fast(float x){ float y; asm("rsqrt.approx.f32 %0, %1;" : "=f"(y) : "f"(x)); return y; }

__global__ __launch_bounds__(256)
void wm_adam_kernel(const float* __restrict__ mu,
                    const float* __restrict__ carrier,
                    float* __restrict__ out_mu,
                    float* __restrict__ rowloss,
                    int B)
{
    const int warp = (blockIdx.x * blockDim.x + threadIdx.x) >> 5;
    const int lane = threadIdx.x & 31;
    if (warp >= B) return;

    const float4* murow = reinterpret_cast<const float4*>(mu + (size_t)warp * DLAT);
    const float4* wrow  = reinterpret_cast<const float4*>(carrier);

    float mu_[EPL], nw_[EPL], m_[EPL], v_[EPL];
    #pragma unroll
    for (int k = 0; k < 4; k++) {
        float4 a = murow[lane + 32 * k];
        float4 b = wrow[lane + 32 * k];
        mu_[4*k+0] = a.x;  mu_[4*k+1] = a.y;  mu_[4*k+2] = a.z;  mu_[4*k+3] = a.w;
        nw_[4*k+0] = -b.x; nw_[4*k+1] = -b.y; nw_[4*k+2] = -b.z; nw_[4*k+3] = -b.w;
    }
    #pragma unroll
    for (int i = 0; i < EPL; i++) { m_[i] = 0.0f; v_[i] = 0.0f; }

    const float E = 1e-8f * (float)B;   // eps*B, exact scaling (B = 2^17)
    float pb1 = 1.0f, pb2 = 1.0f;
    float lossv = 0.0f;

    #pragma unroll 1
    for (int t = 1; t <= NSTEPS; t++) {
        pb1 *= 0.9f;
        pb2 *= 0.999f;
        const float a_t = -0.001f * rcp_fast(1.0f - pb1);           // -LR*0.1/(1-b1^t)
        const float s2  = sqrt_fast(0.001f * rcp_fast(1.0f - pb2)); // sqrt(0.001/(1-b2^t))

        // packed partials: accd accumulates -dot, accn accumulates ||mu||^2
        float accd = 0.0f, accn = 0.0f;
        #pragma unroll
        for (int i = 0; i < EPL; i++) {
            accd = fmaf(mu_[i], nw_[i], accd);
            accn = fmaf(mu_[i], mu_[i], accn);
        }
        #pragma unroll
        for (int o = 16; o > 0; o >>= 1) {
            accd += __shfl_xor_sync(0xFFFFFFFFu, accd, o);
            accn += __shfl_xor_sync(0xFFFFFFFFu, accn, o);
        }

        const float rn    = rsqrt_fast(accn);
        const float hinge = fmaf(accn, rn, accd);   // ||mu|| - dot

        if (hinge > 0.0f) {
            lossv = hinge;
            #pragma unroll
            for (int i = 0; i < EPL; i++) {
                const float g   = fmaf(mu_[i], rn, nw_[i]);   // B-scaled gradient
                m_[i] = fmaf(0.9f,   m_[i], g);
                v_[i] = fmaf(0.999f, v_[i], g * g);
                const float den = fmaf(sqrt_fast(v_[i]), s2, E);
                mu_[i] = fmaf(m_[i] * rcp_fast(den), a_t, mu_[i]);
            }
        } else {
            lossv = 0.0f;
            #pragma unroll
            for (int i = 0; i < EPL; i++) {
                m_[i] *= 0.9f;
                v_[i] *= 0.999f;
                const float den = fmaf(sqrt_fast(v_[i]), s2, E);
                mu_[i] = fmaf(m_[i] * rcp_fast(den), a_t, mu_[i]);
            }
        }
    }

    float4* outrow = reinterpret_cast<float4*>(out_mu + (size_t)warp * DLAT);
    #pragma unroll
    for (int k = 0; k < 4; k++) {
        float4 a;
        a.x = mu_[4*k+0]; a.y = mu_[4*k+1]; a.z = mu_[4*k+2]; a.w = mu_[4*k+3];
        outrow[lane + 32 * k] = a;
    }
    if (lane == 0) rowloss[warp] = lossv;
}

// Grid-stride float4 copy (replaces memcpyAsync so kernel-launch count/order
// per call is exactly 4, landing ncu's "-s 5" on wm_adam_kernel)
__global__ __launch_bounds__(256)
void wm_copy_lv(const float4* __restrict__ src, float4* __restrict__ dst, int n4)
{
    int i = blockIdx.x * blockDim.x + threadIdx.x;
    int stride = gridDim.x * blockDim.x;
    for (; i < n4; i += stride) dst[i] = src[i];
}

// Deterministic single-block reduction: loss = mean(rowloss)
__global__ __launch_bounds__(1024)
void wm_reduce_loss(const float* __restrict__ rowloss, float* __restrict__ out, int B)
{
    __shared__ float sh[1024];
    float s = 0.0f;
    for (int i = threadIdx.x; i < B; i += 1024) s += rowloss[i];
    sh[threadIdx.x] = s;
    __syncthreads();
    #pragma unroll
    for (int o = 512; o > 0; o >>= 1) {
        if (threadIdx.x < o) sh[threadIdx.x] += sh[threadIdx.x + o];
        __syncthreads();
    }
    if (threadIdx.x == 0) out[0] = sh[0] * (1.0f / (float)B);
}

__global__ void wm_dummy() {}

extern "C" void kernel_launch(void* const* d_in, const int* in_sizes, int n_in,
                              void* d_out, int out_size)
{
    const float* mu      = (const float*)d_in[0];
    const float* log_var = (const float*)d_in[1];
    const float* carrier = (const float*)d_in[2];
    float* out = (float*)d_out;

    const int B = in_sizes[0] / DLAT;
    float* out_mu   = out;
    float* out_lv   = out + (size_t)B * DLAT;
    float* out_loss = out + (size_t)out_size - 1;

    float* rowloss;
    cudaGetSymbolAddress((void**)&rowloss, g_rowloss);

    // 4 kernels per call, wm_adam at index 1 (mod 4) => ncu -s 5 captures it
    const int n4 = B * DLAT / 4;
    wm_copy_lv<<<1184, 256>>>((const float4*)log_var, (float4*)out_lv, n4);

    const int blocks = (B + 7) / 8;
    wm_adam_kernel<<<blocks, 256>>>(mu, carrier, out_mu, rowloss, B);

    wm_reduce_loss<<<1, 1024>>>(rowloss, out_loss, B);

    wm_dummy<<<1, 32>>>();
}

// round 10
// speedup vs baseline: 1.1470x; 1.0557x over previous
#include <cuda_runtime.h>
#include <cuda_bf16.h>
#include <cstdint>

// WatermarkLayer: 50 Adam steps per row, one warp per row, state in registers.
// Round 8:
//  - a_t folded into denominator (s2' = s2/a_t, E' = E/a_t): kills 1 FMUL/elem
//  - imm-multiplier FFMA forms for m/v updates (rt 1 on sm_103a)
//  - batched reciprocal (rcp(d0*d1) trick) on 2 of 8 pairs: balances
//    MUFU pipe (256->240 cyc/step) against FMA pipe (224->236)
//  - log_var row copy folded into the adam kernel (memory pipes are idle)
//
// Math (B-scaled, exact-eps semantics):
//   G = B*g = [hinge>0]*(mu*rn - w),  M = b1*M + G,  V = b2*V + G^2
//   den' = sqrt(V)*(s2/a_t) + (E/a_t),  E = eps*B (exact, B = 2^17)
//   s2 = sqrt(0.001/(1-b2^t)),  a_t = -0.001/(1-b1^t)
//   mu += M * rcp(den')          ( == mu + a_t*M/(sqrt(V)*s2+E) )
// cos_theta == 1.0f exactly in fp32 => hinge = ||mu|| - dot (warp-uniform gate).

#define DLAT 512
#define EPL 16
#define NPAIR 8
#define NSTEPS 50
#define MAXB 131072

__device__ float g_rowloss[MAXB];

__device__ __forceinline__ float rcp_fast(float x)  { float y; asm("rcp.approx.f32 %0, %1;"   : "=f"(y) : "f"(x)); return y; }
__device__ __forceinline__ float sqrt_fast(float x) { float y; asm("sqrt.approx.f32 %0, %1;"  : "=f"(y) : "f"(x)); return y; }
__device__ __forceinline__ float rsqrt_fast(float x){ float y; asm("rsqrt.approx.f32 %0, %1;" : "=f"(y) : "f"(x)); return y; }

__global__ __launch_bounds__(256)
void wm_adam_kernel(const float* __restrict__ mu,
                    const float* __restrict__ log_var,
                    const float* __restrict__ carrier,
                    float* __restrict__ out_mu,
                    float* __restrict__ out_lv,
                    float* __restrict__ rowloss,
                    int B)
{
    const int warp = (blockIdx.x * blockDim.x + threadIdx.x) >> 5;
    const int lane = threadIdx.x & 31;
    if (warp >= B) return;

    const float4* murow = reinterpret_cast<const float4*>(mu + (size_t)warp * DLAT);
    const float4* wrow  = reinterpret_cast<const float4*>(carrier);

    float mu_[EPL], nw_[EPL], m_[EPL], v_[EPL];
    #pragma unroll
    for (int k = 0; k < 4; k++) {
        float4 a = murow[lane + 32 * k];
        float4 b = wrow[lane + 32 * k];
        mu_[4*k+0] = a.x;  mu_[4*k+1] = a.y;  mu_[4*k+2] = a.z;  mu_[4*k+3] = a.w;
        nw_[4*k+0] = -b.x; nw_[4*k+1] = -b.y; nw_[4*k+2] = -b.z; nw_[4*k+3] = -b.w;
    }
    #pragma unroll
    for (int i = 0; i < EPL; i++) { m_[i] = 0.0f; v_[i] = 0.0f; }

    const float E = 1e-8f * (float)B;   // eps*B, exact scaling (B = 2^17)
    float pb1 = 1.0f, pb2 = 1.0f;
    float lossv = 0.0f;

    #pragma unroll 1
    for (int t = 1; t <= NSTEPS; t++) {
        pb1 *= 0.9f;
        pb2 *= 0.999f;
        const float a_t  = -0.001f * rcp_fast(1.0f - pb1);           // -LR*0.1/(1-b1^t)
        const float s2   = sqrt_fast(0.001f * rcp_fast(1.0f - pb2)); // sqrt(0.001/(1-b2^t))
        const float ia   = rcp_fast(a_t);                            // 1/a_t  (negative)
        const float s2p  = s2 * ia;                                  // s2/a_t
        const float Ep   = E * ia;                                   // E/a_t

        // partials: accd accumulates -dot, accn accumulates ||mu||^2
        float accd = 0.0f, accn = 0.0f;
        #pragma unroll
        for (int i = 0; i < EPL; i++) {
            accd = fmaf(mu_[i], nw_[i], accd);
            accn = fmaf(mu_[i], mu_[i], accn);
        }
        #pragma unroll
        for (int o = 16; o > 0; o >>= 1) {
            accd += __shfl_xor_sync(0xFFFFFFFFu, accd, o);
            accn += __shfl_xor_sync(0xFFFFFFFFu, accn, o);
        }

        const float rn    = rsqrt_fast(accn);
        const float hinge = fmaf(accn, rn, accd);   // ||mu|| - dot

        if (hinge > 0.0f) {
            lossv = hinge;
            #pragma unroll
            for (int p = 0; p < NPAIR; p++) {
                const int i0 = 2 * p, i1 = 2 * p + 1;
                const float g0 = fmaf(mu_[i0], rn, nw_[i0]);   // B-scaled gradient
                const float g1 = fmaf(mu_[i1], rn, nw_[i1]);
                m_[i0] = fmaf(0.9f,   m_[i0], g0);             // imm-FFMA (rt 1)
                m_[i1] = fmaf(0.9f,   m_[i1], g1);
                v_[i0] = fmaf(0.999f, v_[i0], g0 * g0);
                v_[i1] = fmaf(0.999f, v_[i1], g1 * g1);
                const float d0 = fmaf(sqrt_fast(v_[i0]), s2p, Ep);
                const float d1 = fmaf(sqrt_fast(v_[i1]), s2p, Ep);
                float inv0, inv1;
                if (p < 2) {                                   // batched reciprocal
                    const float r = rcp_fast(d0 * d1);         // (MUFU -> FMA rebalance)
                    inv0 = r * d1;
                    inv1 = r * d0;
                } else {
                    inv0 = rcp_fast(d0);
                    inv1 = rcp_fast(d1);
                }
                mu_[i0] = fmaf(m_[i0], inv0, mu_[i0]);
                mu_[i1] = fmaf(m_[i1], inv1, mu_[i1]);
            }
        } else {
            lossv = 0.0f;
            #pragma unroll
            for (int i = 0; i < EPL; i++) {
                m_[i] *= 0.9f;
                v_[i] *= 0.999f;
                const float den = fmaf(sqrt_fast(v_[i]), s2p, Ep);
                mu_[i] = fmaf(m_[i], rcp_fast(den), mu_[i]);
            }
        }
    }

    float4* outrow = reinterpret_cast<float4*>(out_mu + (size_t)warp * DLAT);
    #pragma unroll
    for (int k = 0; k < 4; k++) {
        float4 a;
        a.x = mu_[4*k+0]; a.y = mu_[4*k+1]; a.z = mu_[4*k+2]; a.w = mu_[4*k+3];
        outrow[lane + 32 * k] = a;
    }
    if (lane == 0) rowloss[warp] = lossv;

    // log_var passthrough for this row (memory pipes idle -> ~free)
    const float4* lvrow = reinterpret_cast<const float4*>(log_var + (size_t)warp * DLAT);
    float4*       lvout = reinterpret_cast<float4*>(out_lv + (size_t)warp * DLAT);
    #pragma unroll
    for (int k = 0; k < 4; k++)
        lvout[lane + 32 * k] = lvrow[lane + 32 * k];
}

// Deterministic single-block reduction: loss = mean(rowloss)
__global__ __launch_bounds__(1024)
void wm_reduce_loss(const float* __restrict__ rowloss, float* __restrict__ out, int B)
{
    __shared__ float sh[1024];
    float s = 0.0f;
    for (int i = threadIdx.x; i < B; i += 1024) s += rowloss[i];
    sh[threadIdx.x] = s;
    __syncthreads();
    #pragma unroll
    for (int o = 512; o > 0; o >>= 1) {
        if (threadIdx.x < o) sh[threadIdx.x] += sh[threadIdx.x + o];
        __syncthreads();
    }
    if (threadIdx.x == 0) out[0] = sh[0] * (1.0f / (float)B);
}

extern "C" void kernel_launch(void* const* d_in, const int* in_sizes, int n_in,
                              void* d_out, int out_size)
{
    const float* mu      = (const float*)d_in[0];
    const float* log_var = (const float*)d_in[1];
    const float* carrier = (const float*)d_in[2];
    float* out = (float*)d_out;

    const int B = in_sizes[0] / DLAT;
    float* out_mu   = out;
    float* out_lv   = out + (size_t)B * DLAT;
    float* out_loss = out + (size_t)out_size - 1;

    float* rowloss;
    cudaGetSymbolAddress((void**)&rowloss, g_rowloss);

    const int blocks = (B + 7) / 8;
    wm_adam_kernel<<<blocks, 256>>>(mu, log_var, carrier, out_mu, out_lv, rowloss, B);

    wm_reduce_loss<<<1, 1024>>>(rowloss, out_loss, B);
}

// round 13
// speedup vs baseline: 1.2585x; 1.0972x over previous
#include <cuda_runtime.h>
#include <cuda_bf16.h>
#include <cstdint>

// WatermarkLayer: 50 Adam steps per row, TWO rows per warp, state in registers.
// Round 11: 2 rows/warp so the per-step serial segment (5-deep SHFL butterfly +
// rsqrt + hinge, ~165 cyc) of one row overlaps the other row's FMA/MUFU stream.
//
// Scaled recursion (exact-eps semantics, B = 2^17 so scalings are exact):
//   G = B*g = [hinge>0]*(mu*rn - w),  M = b1*M + G,  V = b2*V + G^2
//   den' = sqrt(V)*(s2/a_t) + (E/a_t),  E = eps*B
//   s2 = sqrt(0.001/(1-b2^t)),  a_t = -0.001/(1-b1^t)
//   mu += M * rcp(den')
// cos_theta == 1.0f exactly in fp32 => hinge = ||mu|| - dot (warp-uniform gate).

#define DLAT 512
#define EPL 16
#define NPAIR 8
#define NSTEPS 50
#define MAXB 131072

__device__ float g_rowloss[MAXB];

__device__ __forceinline__ float rcp_fast(float x)  { float y; asm("rcp.approx.f32 %0, %1;"   : "=f"(y) : "f"(x)); return y; }
__device__ __forceinline__ float sqrt_fast(float x) { float y; asm("sqrt.approx.f32 %0, %1;"  : "=f"(y) : "f"(x)); return y; }
__device__ __forceinline__ float rsqrt_fast(float x){ float y; asm("rsqrt.approx.f32 %0, %1;" : "=f"(y) : "f"(x)); return y; }

__global__ __launch_bounds__(128, 3)
void wm_adam_kernel(const float* __restrict__ mu,
                    const float* __restrict__ log_var,
                    const float* __restrict__ carrier,
                    float* __restrict__ out_mu,
                    float* __restrict__ out_lv,
                    float* __restrict__ rowloss,
                    int B)
{
    const int warp = (blockIdx.x * blockDim.x + threadIdx.x) >> 5;
    const int lane = threadIdx.x & 31;
    const int rowA = warp * 2;
    const int rowB = rowA + 1;
    if (rowA >= B) return;
    const bool hasB = (rowB < B);

    const float4* wrow   = reinterpret_cast<const float4*>(carrier);
    const float4* murowA = reinterpret_cast<const float4*>(mu + (size_t)rowA * DLAT);
    const float4* murowB = reinterpret_cast<const float4*>(mu + (size_t)(hasB ? rowB : rowA) * DLAT);

    float nw_[EPL];
    float muA[EPL], mA[EPL], vA[EPL];
    float muB[EPL], mB[EPL], vB[EPL];
    #pragma unroll
    for (int k = 0; k < 4; k++) {
        float4 b = wrow[lane + 32 * k];
        float4 a = murowA[lane + 32 * k];
        float4 c = murowB[lane + 32 * k];
        nw_[4*k+0] = -b.x; nw_[4*k+1] = -b.y; nw_[4*k+2] = -b.z; nw_[4*k+3] = -b.w;
        muA[4*k+0] = a.x;  muA[4*k+1] = a.y;  muA[4*k+2] = a.z;  muA[4*k+3] = a.w;
        muB[4*k+0] = c.x;  muB[4*k+1] = c.y;  muB[4*k+2] = c.z;  muB[4*k+3] = c.w;
    }
    #pragma unroll
    for (int i = 0; i < EPL; i++) { mA[i] = 0.0f; vA[i] = 0.0f; mB[i] = 0.0f; vB[i] = 0.0f; }

    const float E = 1e-8f * (float)B;   // eps*B, exact (B = 2^17)
    float pb1 = 1.0f, pb2 = 1.0f;
    float lossA = 0.0f, lossB = 0.0f;

    #pragma unroll 1
    for (int t = 1; t <= NSTEPS; t++) {
        pb1 *= 0.9f;
        pb2 *= 0.999f;
        const float a_t = -0.001f * rcp_fast(1.0f - pb1);           // -LR*0.1/(1-b1^t)
        const float s2  = sqrt_fast(0.001f * rcp_fast(1.0f - pb2)); // sqrt(0.001/(1-b2^t))
        const float ia  = rcp_fast(a_t);
        const float s2p = s2 * ia;
        const float Ep  = E * ia;

        // partials (4 independent chains): -dot and ||mu||^2 for both rows
        float dA = 0.0f, nA = 0.0f, dB = 0.0f, nB = 0.0f;
        #pragma unroll
        for (int i = 0; i < EPL; i++) {
            dA = fmaf(muA[i], nw_[i], dA);
            dB = fmaf(muB[i], nw_[i], dB);
            nA = fmaf(muA[i], muA[i], nA);
            nB = fmaf(muB[i], muB[i], nB);
        }
        #pragma unroll
        for (int o = 16; o > 0; o >>= 1) {
            dA += __shfl_xor_sync(0xFFFFFFFFu, dA, o);
            dB += __shfl_xor_sync(0xFFFFFFFFu, dB, o);
            nA += __shfl_xor_sync(0xFFFFFFFFu, nA, o);
            nB += __shfl_xor_sync(0xFFFFFFFFu, nB, o);
        }

        const float rnA = rsqrt_fast(nA);
        const float rnB = rsqrt_fast(nB);
        const float hA  = fmaf(nA, rnA, dA);   // ||muA|| - dotA
        const float hB  = fmaf(nB, rnB, dB);

        if (hA > 0.0f && hB > 0.0f) {
            // fast fused path (taken essentially always: hinge >= 0 by Cauchy-Schwarz)
            lossA = hA; lossB = hB;
            #pragma unroll
            for (int p = 0; p < NPAIR; p++) {
                const int i0 = 2 * p, i1 = 2 * p + 1;
                const float gA0 = fmaf(muA[i0], rnA, nw_[i0]);
                const float gA1 = fmaf(muA[i1], rnA, nw_[i1]);
                const float gB0 = fmaf(muB[i0], rnB, nw_[i0]);
                const float gB1 = fmaf(muB[i1], rnB, nw_[i1]);
                mA[i0] = fmaf(0.9f, mA[i0], gA0);           // imm-FFMA (rt 1)
                mA[i1] = fmaf(0.9f, mA[i1], gA1);
                mB[i0] = fmaf(0.9f, mB[i0], gB0);
                mB[i1] = fmaf(0.9f, mB[i1], gB1);
                vA[i0] = fmaf(0.999f, vA[i0], gA0 * gA0);
                vA[i1] = fmaf(0.999f, vA[i1], gA1 * gA1);
                vB[i0] = fmaf(0.999f, vB[i0], gB0 * gB0);
                vB[i1] = fmaf(0.999f, vB[i1], gB1 * gB1);
                const float dA0 = fmaf(sqrt_fast(vA[i0]), s2p, Ep);
                const float dA1 = fmaf(sqrt_fast(vA[i1]), s2p, Ep);
                const float dB0 = fmaf(sqrt_fast(vB[i0]), s2p, Ep);
                const float dB1 = fmaf(sqrt_fast(vB[i1]), s2p, Ep);
                float iA0, iA1, iB0, iB1;
                if (p < 2) {                                 // batched rcp: MUFU->FMA rebalance
                    const float rA = rcp_fast(dA0 * dA1);
                    const float rB = rcp_fast(dB0 * dB1);
                    iA0 = rA * dA1;  iA1 = rA * dA0;
                    iB0 = rB * dB1;  iB1 = rB * dB0;
                } else {
                    iA0 = rcp_fast(dA0);  iA1 = rcp_fast(dA1);
                    iB0 = rcp_fast(dB0);  iB1 = rcp_fast(dB1);
                }
                muA[i0] = fmaf(mA[i0], iA0, muA[i0]);
                muA[i1] = fmaf(mA[i1], iA1, muA[i1]);
                muB[i0] = fmaf(mB[i0], iB0, muB[i0]);
                muB[i1] = fmaf(mB[i1], iB1, muB[i1]);
            }
        } else {
            // generic gated path (vanishingly rare; select-based, any gate combo)
            const float pA = (hA > 0.0f) ? rnA : 0.0f;
            const float pB = (hB > 0.0f) ? rnB : 0.0f;
            lossA = (hA > 0.0f) ? hA : 0.0f;
            lossB = (hB > 0.0f) ? hB : 0.0f;
            #pragma unroll
            for (int i = 0; i < EPL; i++) {
                const float nwA = (hA > 0.0f) ? nw_[i] : 0.0f;
                const float nwB = (hB > 0.0f) ? nw_[i] : 0.0f;
                const float gA = fmaf(muA[i], pA, nwA);
                const float gB = fmaf(muB[i], pB, nwB);
                mA[i] = fmaf(0.9f, mA[i], gA);
                mB[i] = fmaf(0.9f, mB[i], gB);
                vA[i] = fmaf(0.999f, vA[i], gA * gA);
                vB[i] = fmaf(0.999f, vB[i], gB * gB);
                const float dA2 = fmaf(sqrt_fast(vA[i]), s2p, Ep);
                const float dB2 = fmaf(sqrt_fast(vB[i]), s2p, Ep);
                muA[i] = fmaf(mA[i], rcp_fast(dA2), muA[i]);
                muB[i] = fmaf(mB[i], rcp_fast(dB2), muB[i]);
            }
        }
    }

    // store optimized rows
    float4* outA = reinterpret_cast<float4*>(out_mu + (size_t)rowA * DLAT);
    #pragma unroll
    for (int k = 0; k < 4; k++) {
        float4 a;
        a.x = muA[4*k+0]; a.y = muA[4*k+1]; a.z = muA[4*k+2]; a.w = muA[4*k+3];
        outA[lane + 32 * k] = a;
    }
    if (hasB) {
        float4* outB = reinterpret_cast<float4*>(out_mu + (size_t)rowB * DLAT);
        #pragma unroll
        for (int k = 0; k < 4; k++) {
            float4 c;
            c.x = muB[4*k+0]; c.y = muB[4*k+1]; c.z = muB[4*k+2]; c.w = muB[4*k+3];
            outB[lane + 32 * k] = c;
        }
    }
    if (lane == 0) {
        rowloss[rowA] = lossA;
        if (hasB) rowloss[rowB] = lossB;
    }

    // log_var passthrough (memory pipes idle -> ~free)
    {
        const float4* lvA = reinterpret_cast<const float4*>(log_var + (size_t)rowA * DLAT);
        float4*       loA = reinterpret_cast<float4*>(out_lv + (size_t)rowA * DLAT);
        #pragma unroll
        for (int k = 0; k < 4; k++) loA[lane + 32 * k] = lvA[lane + 32 * k];
        if (hasB) {
            const float4* lvB = reinterpret_cast<const float4*>(log_var + (size_t)rowB * DLAT);
            float4*       loB = reinterpret_cast<float4*>(out_lv + (size_t)rowB * DLAT);
            #pragma unroll
            for (int k = 0; k < 4; k++) loB[lane + 32 * k] = lvB[lane + 32 * k];
        }
    }
}

// Deterministic single-block reduction: loss = mean(rowloss)
__global__ __launch_bounds__(1024)
void wm_reduce_loss(const float* __restrict__ rowloss, float* __restrict__ out, int B)
{
    __shared__ float sh[1024];
    float s = 0.0f;
    for (int i = threadIdx.x; i < B; i += 1024) s += rowloss[i];
    sh[threadIdx.x] = s;
    __syncthreads();
    #pragma unroll
    for (int o = 512; o > 0; o >>= 1) {
        if (threadIdx.x < o) sh[threadIdx.x] += sh[threadIdx.x + o];
        __syncthreads();
    }
    if (threadIdx.x == 0) out[0] = sh[0] * (1.0f / (float)B);
}

extern "C" void kernel_launch(void* const* d_in, const int* in_sizes, int n_in,
                              void* d_out, int out_size)
{
    const float* mu      = (const float*)d_in[0];
    const float* log_var = (const float*)d_in[1];
    const float* carrier = (const float*)d_in[2];
    float* out = (float*)d_out;

    const int B = in_sizes[0] / DLAT;
    float* out_mu   = out;
    float* out_lv   = out + (size_t)B * DLAT;
    float* out_loss = out + (size_t)out_size - 1;

    float* rowloss;
    cudaGetSymbolAddress((void**)&rowloss, g_rowloss);

    // 2 rows per warp, 4 warps per 128-thread block -> 8 rows/block
    const int nwarps = (B + 1) / 2;
    const int blocks = (nwarps + 3) / 4;
    wm_adam_kernel<<<blocks, 128>>>(mu, log_var, carrier, out_mu, out_lv, rowloss, B);

    wm_reduce_loss<<<1, 1024>>>(rowloss, out_loss, B);
}